// round 15
// baseline (speedup 1.0000x reference)
#include <cuda_runtime.h>
#include <cuda_fp16.h>

#define NMAX 50000
#define BCAP 64
#define OVF_MAX 4096
#define DIN 128
#define DHID 128
#define DOUT 64

// g_degi is zero-initialized at module load and re-zeroed by k_scatter2 at the
// end of every call, so k_prep's atomicAdd-based bucketing sees zeros on every
// call (correctness run and every graph replay alike).
__device__ int    g_degi[NMAX];
__device__ int    g_srcs[NMAX * BCAP];
__device__ int2   g_ovf[OVF_MAX];
__device__ int    g_ovf_cnt;
__device__ __half g_h[NMAX * DHID];      // fp16: dinv * (x @ W1)
__device__ __half g_in2[NMAX * DHID];    // fp16: relu(dinv*sum + b1)
__device__ __half g_h2[NMAX * DOUT];     // fp16: dinv * (in2 @ W2)
__device__ __half g_w1t[DHID * DIN];     // W1^T [n][k] fp16
__device__ __half g_w2t[DOUT * DHID];    // W2^T [n][k] fp16

__device__ __forceinline__ void mma16(float* c, const unsigned* a, const unsigned* b) {
    asm volatile(
        "mma.sync.aligned.m16n8k16.row.col.f32.f16.f16.f32 "
        "{%0,%1,%2,%3},{%4,%5,%6,%7},{%8,%9},{%0,%1,%2,%3};"
        : "+f"(c[0]), "+f"(c[1]), "+f"(c[2]), "+f"(c[3])
        : "r"(a[0]), "r"(a[1]), "r"(a[2]), "r"(a[3]), "r"(b[0]), "r"(b[1]));
}

__device__ __forceinline__ float dinv_of(int row) {
    return rsqrtf((float)(g_degi[row] + 1));
}

__device__ __forceinline__ void acc4_u2(float* acc, uint2 u) {
    float2 f0 = __half22float2(*(__half2*)&u.x);
    float2 f1 = __half22float2(*(__half2*)&u.y);
    acc[0] += f0.x; acc[1] += f0.y; acc[2] += f1.x; acc[3] += f1.y;
}

__device__ __forceinline__ void acc4_pair(float* acc, uint2 a, uint2 b) {
    __half2 p0 = __hadd2(*(__half2*)&a.x, *(__half2*)&b.x);
    __half2 p1 = __hadd2(*(__half2*)&a.y, *(__half2*)&b.y);
    float2 f0 = __half22float2(p0);
    float2 f1 = __half22float2(p1);
    acc[0] += f0.x; acc[1] += f0.y; acc[2] += f1.x; acc[3] += f1.y;
}

__device__ __forceinline__ void acc8_u4(float* acc, uint4 a) {
    float2 f0 = __half22float2(*(__half2*)&a.x);
    float2 f1 = __half22float2(*(__half2*)&a.y);
    float2 f2 = __half22float2(*(__half2*)&a.z);
    float2 f3 = __half22float2(*(__half2*)&a.w);
    acc[0] += f0.x; acc[1] += f0.y; acc[2] += f1.x; acc[3] += f1.y;
    acc[4] += f2.x; acc[5] += f2.y; acc[6] += f3.x; acc[7] += f3.y;
}

__device__ __forceinline__ void acc8_pair(float* acc, uint4 a, uint4 b) {
    __half2 p0 = __hadd2(*(__half2*)&a.x, *(__half2*)&b.x);
    __half2 p1 = __hadd2(*(__half2*)&a.y, *(__half2*)&b.y);
    __half2 p2 = __hadd2(*(__half2*)&a.z, *(__half2*)&b.z);
    __half2 p3 = __hadd2(*(__half2*)&a.w, *(__half2*)&b.w);
    float2 f0 = __half22float2(p0), f1 = __half22float2(p1);
    float2 f2 = __half22float2(p2), f3 = __half22float2(p3);
    acc[0] += f0.x; acc[1] += f0.y; acc[2] += f1.x; acc[3] += f1.y;
    acc[4] += f2.x; acc[5] += f2.y; acc[6] += f3.x; acc[7] += f3.y;
}

// ---------------------------------------------------------------------------
// k_prep: edge bucketing blocks + weight transpose blocks (single launch).
// ---------------------------------------------------------------------------
__global__ void k_prep(const void* ei, int E,
                       const float* __restrict__ W1, const float* __restrict__ W2,
                       int nEdgeBlocks) {
    if ((int)blockIdx.x >= nEdgeBlocks) {
        int i = (blockIdx.x - nEdgeBlocks) * 256 + threadIdx.x;
        if (i < DIN * DHID) {
            int nn = i >> 7, k = i & 127;
            g_w1t[nn * DIN + k] = __float2half(W1[k * DHID + nn]);
        }
        int j = i - DIN * DHID;
        if (j >= 0 && j < DHID * DOUT) {
            int nn = j >> 7, k = j & 127;
            g_w2t[nn * DHID + k] = __float2half(W2[k * DOUT + nn]);
        }
        return;
    }

    __shared__ int s_is64;
    if (threadIdx.x == 0) {
        const unsigned* p32 = (const unsigned*)ei;
        int ok = 1;
        for (int j = 0; j < 64; j++)
            if (p32[2 * j + 1] != 0u) ok = 0;
        s_is64 = ok;
    }
    __syncthreads();
    int is64 = s_is64;

    int e = (blockIdx.x * blockDim.x + threadIdx.x) * 2;
    if (e >= E) return;
    int src0, dst0, src1 = 0, dst1 = 0;
    int has1 = (e + 1 < E);
    if (is64) {
        const long long* p = (const long long*)ei;
        src0 = (int)p[e];
        dst0 = (int)p[E + e];
        if (has1) { src1 = (int)p[e + 1]; dst1 = (int)p[E + e + 1]; }
    } else {
        const int* p = (const int*)ei;
        src0 = p[e];
        dst0 = p[E + e];
        if (has1) { src1 = p[e + 1]; dst1 = p[E + e + 1]; }
    }
    int slot0 = atomicAdd(&g_degi[dst0], 1);
    if (slot0 < BCAP) {
        g_srcs[dst0 * BCAP + slot0] = src0;
    } else {
        int o = atomicAdd(&g_ovf_cnt, 1);
        if (o < OVF_MAX) g_ovf[o] = make_int2(src0, dst0);
    }
    if (has1) {
        int slot1 = atomicAdd(&g_degi[dst1], 1);
        if (slot1 < BCAP) {
            g_srcs[dst1 * BCAP + slot1] = src1;
        } else {
            int o = atomicAdd(&g_ovf_cnt, 1);
            if (o < OVF_MAX) g_ovf[o] = make_int2(src1, dst1);
        }
    }
}

// ---------------------------------------------------------------------------
// GEMM1: CTA 64x128, 8 warps (2m x 4n), warp tile 32x32.
// fused fp32->fp16 x load, full-K single-sync.
// ---------------------------------------------------------------------------
__global__ __launch_bounds__(256) void k_gemm1(const float* __restrict__ x, int n) {
    __shared__ unsigned xs[64][68];
    __shared__ unsigned ws[128][68];

    const int t = threadIdx.x;
    const int lane = t & 31;
    const int warp = t >> 5;
    const int wm = warp & 1;       // 0..1 (32-row subtile)
    const int wn = warp >> 1;      // 0..3 (32-col subtile)
    const int tg = lane & 3;
    const int gi = lane >> 2;
    const int row0 = blockIdx.x * 64;

    // x tile: 64 rows x 32 float4 = 2048 float4
#pragma unroll
    for (int i = 0; i < 8; i++) {
        int idx = t + i * 256;
        int r = idx >> 5, q = idx & 31;
        float4 v = make_float4(0.f, 0.f, 0.f, 0.f);
        if (row0 + r < n)
            v = *(const float4*)&x[(size_t)(row0 + r) * DIN + q * 4];
        uint2 o;
        *(__half2*)&o.x = __floats2half2_rn(v.x, v.y);
        *(__half2*)&o.y = __floats2half2_rn(v.z, v.w);
        *(uint2*)&xs[r][q * 2] = o;
    }
    // W1^T: 128 cols x 16 uint4 = 2048
#pragma unroll
    for (int i = 0; i < 8; i++) {
        int idx = t + i * 256;
        int c = idx >> 4, q = idx & 15;
        uint4 v = *(const uint4*)&g_w1t[c * DIN + q * 8];
        *(uint4*)&ws[c][q * 4] = v;
    }
    __syncthreads();

    float acc[2][4][4];
#pragma unroll
    for (int m = 0; m < 2; m++)
#pragma unroll
        for (int nn = 0; nn < 4; nn++)
#pragma unroll
            for (int j = 0; j < 4; j++) acc[m][nn][j] = 0.f;

#pragma unroll
    for (int ks = 0; ks < 8; ks++) {
        int k0 = ks * 8;
        unsigned a[2][4];
#pragma unroll
        for (int m = 0; m < 2; m++) {
            int r = wm * 32 + m * 16 + gi;
            a[m][0] = xs[r][k0 + tg];
            a[m][1] = xs[r + 8][k0 + tg];
            a[m][2] = xs[r][k0 + 4 + tg];
            a[m][3] = xs[r + 8][k0 + 4 + tg];
        }
#pragma unroll
        for (int nn = 0; nn < 4; nn++) {
            int c = wn * 32 + nn * 8 + gi;
            unsigned b[2];
            b[0] = ws[c][k0 + tg];
            b[1] = ws[c][k0 + 4 + tg];
            mma16(acc[0][nn], a[0], b);
            mma16(acc[1][nn], a[1], b);
        }
    }

#pragma unroll
    for (int m = 0; m < 2; m++) {
#pragma unroll
        for (int h = 0; h < 2; h++) {
            int row = row0 + wm * 32 + m * 16 + gi + h * 8;
            if (row < n) {
                float d = dinv_of(row);
#pragma unroll
                for (int nn = 0; nn < 4; nn++) {
                    int col = wn * 32 + nn * 8 + tg * 2;
                    __half2 o = __floats2half2_rn(acc[m][nn][h * 2 + 0] * d,
                                                  acc[m][nn][h * 2 + 1] * d);
                    *(__half2*)&g_h[(size_t)row * DHID + col] = o;
                }
            }
        }
    }
}

// ---------------------------------------------------------------------------
// scatter1 + layer-2 input prep (FROZEN shape): 1 warp/node.
// ---------------------------------------------------------------------------
__global__ __launch_bounds__(256, 8) void k_scatter1(const float* __restrict__ b1, int n) {
    int w = (blockIdx.x * blockDim.x + threadIdx.x) >> 5;
    int lane = threadIdx.x & 31;
    if (w >= n) return;
    int deg = g_degi[w];
    int nb = min(deg, BCAP);

    float acc[4] = {0.f, 0.f, 0.f, 0.f};
    acc4_u2(acc, *(const uint2*)&g_h[(size_t)w * DHID + lane * 4]);

    for (int base = 0; base < nb; base += 32) {
        int cnt = min(nb - base, 32);
        int s = (lane < cnt) ? g_srcs[w * BCAP + base + lane] : 0;
        int i = 0;
        for (; i + 4 <= cnt; i += 4) {
            int s0 = __shfl_sync(0xffffffffu, s, i);
            int s1 = __shfl_sync(0xffffffffu, s, i + 1);
            int s2 = __shfl_sync(0xffffffffu, s, i + 2);
            int s3 = __shfl_sync(0xffffffffu, s, i + 3);
            uint2 u0 = *(const uint2*)&g_h[(size_t)s0 * DHID + lane * 4];
            uint2 u1 = *(const uint2*)&g_h[(size_t)s1 * DHID + lane * 4];
            uint2 u2 = *(const uint2*)&g_h[(size_t)s2 * DHID + lane * 4];
            uint2 u3 = *(const uint2*)&g_h[(size_t)s3 * DHID + lane * 4];
            acc4_pair(acc, u0, u1);
            acc4_pair(acc, u2, u3);
        }
        if (i + 2 <= cnt) {
            int s0 = __shfl_sync(0xffffffffu, s, i);
            int s1 = __shfl_sync(0xffffffffu, s, i + 1);
            uint2 u0 = *(const uint2*)&g_h[(size_t)s0 * DHID + lane * 4];
            uint2 u1 = *(const uint2*)&g_h[(size_t)s1 * DHID + lane * 4];
            acc4_pair(acc, u0, u1);
            i += 2;
        }
        if (i < cnt) {
            int s0 = __shfl_sync(0xffffffffu, s, i);
            acc4_u2(acc, *(const uint2*)&g_h[(size_t)s0 * DHID + lane * 4]);
        }
    }
    if (deg > BCAP) {  // correctness fallback, practically never taken
        int oc = min(g_ovf_cnt, OVF_MAX);
        for (int i = 0; i < oc; i++) {
            int2 ed = g_ovf[i];
            if (ed.y == w)
                acc4_u2(acc, *(const uint2*)&g_h[(size_t)ed.x * DHID + lane * 4]);
        }
    }
    float d = dinv_of(w);
    float4 bb = *(const float4*)&b1[lane * 4];
    float v0 = fmaxf(d * acc[0] + bb.x, 0.f);
    float v1 = fmaxf(d * acc[1] + bb.y, 0.f);
    float v2 = fmaxf(d * acc[2] + bb.z, 0.f);
    float v3 = fmaxf(d * acc[3] + bb.w, 0.f);
    uint2 o;
    *(__half2*)&o.x = __floats2half2_rn(v0, v1);
    *(__half2*)&o.y = __floats2half2_rn(v2, v3);
    *(uint2*)&g_in2[(size_t)w * DHID + lane * 4] = o;
}

// ---------------------------------------------------------------------------
// GEMM2: CTA 64x64, 8 warps (4m x 2n), warp tile 16x32. smem 34.8KB.
// ---------------------------------------------------------------------------
__global__ __launch_bounds__(256) void k_gemm2(int n) {
    __shared__ unsigned xs[64][68];
    __shared__ unsigned ws[64][68];

    const int t = threadIdx.x;
    const int lane = t & 31;
    const int warp = t >> 5;
    const int wm = warp >> 1;      // 0..3 (16-row subtile)
    const int wn = warp & 1;       // 0..1 (32-col subtile)
    const int tg = lane & 3;
    const int gi = lane >> 2;
    const int row0 = blockIdx.x * 64;

    // xs: 64 rows x 16 uint4 = 1024
#pragma unroll
    for (int i = 0; i < 4; i++) {
        int idx = t + i * 256;
        int r = idx >> 4, q = idx & 15;
        uint4 v = make_uint4(0u, 0u, 0u, 0u);
        if (row0 + r < n)
            v = *(const uint4*)&g_in2[(size_t)(row0 + r) * DHID + q * 8];
        *(uint4*)&xs[r][q * 4] = v;
    }
    // ws: 64 cols x 16 uint4 = 1024
#pragma unroll
    for (int i = 0; i < 4; i++) {
        int idx = t + i * 256;
        int c = idx >> 4, q = idx & 15;
        uint4 v = *(const uint4*)&g_w2t[c * DHID + q * 8];
        *(uint4*)&ws[c][q * 4] = v;
    }
    __syncthreads();

    float acc[4][4];
#pragma unroll
    for (int nn = 0; nn < 4; nn++)
#pragma unroll
        for (int j = 0; j < 4; j++) acc[nn][j] = 0.f;

#pragma unroll
    for (int ks = 0; ks < 8; ks++) {
        int k0 = ks * 8;
        unsigned a[4];
        int r = wm * 16 + gi;
        a[0] = xs[r][k0 + tg];
        a[1] = xs[r + 8][k0 + tg];
        a[2] = xs[r][k0 + 4 + tg];
        a[3] = xs[r + 8][k0 + 4 + tg];
#pragma unroll
        for (int nn = 0; nn < 4; nn++) {
            int c = wn * 32 + nn * 8 + gi;
            unsigned b[2];
            b[0] = ws[c][k0 + tg];
            b[1] = ws[c][k0 + 4 + tg];
            mma16(acc[nn], a, b);
        }
    }

#pragma unroll
    for (int h = 0; h < 2; h++) {
        int row = row0 + wm * 16 + gi + h * 8;
        if (row < n) {
            float d = dinv_of(row);
#pragma unroll
            for (int nn = 0; nn < 4; nn++) {
                int col = wn * 32 + nn * 8 + tg * 2;
                __half2 o = __floats2half2_rn(acc[nn][h * 2 + 0] * d,
                                              acc[nn][h * 2 + 1] * d);
                *(__half2*)&g_h2[(size_t)row * DOUT + col] = o;
            }
        }
    }
}

// ---------------------------------------------------------------------------
// scatter2 + final (FROZEN shape): 4 nodes/warp, 8 lanes each.
// Also re-zeros g_degi[node] so k_prep sees zeros next call.
// ---------------------------------------------------------------------------
__global__ __launch_bounds__(256, 8) void k_scatter2(const float* __restrict__ b2,
                                                     float* __restrict__ out, int n) {
    int gw = (blockIdx.x * blockDim.x + threadIdx.x) >> 5;
    int lane = threadIdx.x & 31;
    int q   = lane >> 3;
    int sub = lane & 7;
    int node = gw * 4 + q;
    if (node >= n) return;
    unsigned gmask = 0xFFu << (q * 8);
    int deg = g_degi[node];
    int nb = min(deg, BCAP);

    float acc[8];
#pragma unroll
    for (int j = 0; j < 8; j++) acc[j] = 0.f;
    acc8_u4(acc, *(const uint4*)&g_h2[(size_t)node * DOUT + sub * 8]);

    for (int base = 0; base < nb; base += 8) {
        int cnt = min(nb - base, 8);
        int s = (sub < cnt) ? g_srcs[node * BCAP + base + sub] : 0;
        int i = 0;
        for (; i + 2 <= cnt; i += 2) {
            int s0 = __shfl_sync(gmask, s, q * 8 + i);
            int s1 = __shfl_sync(gmask, s, q * 8 + i + 1);
            uint4 a = *(const uint4*)&g_h2[(size_t)s0 * DOUT + sub * 8];
            uint4 b = *(const uint4*)&g_h2[(size_t)s1 * DOUT + sub * 8];
            acc8_pair(acc, a, b);
        }
        if (i < cnt) {
            int s0 = __shfl_sync(gmask, s, q * 8 + i);
            acc8_u4(acc, *(const uint4*)&g_h2[(size_t)s0 * DOUT + sub * 8]);
        }
    }
    if (deg > BCAP) {
        int oc = min(g_ovf_cnt, OVF_MAX);
        for (int i = 0; i < oc; i++) {
            int2 ed = g_ovf[i];
            if (ed.y == node)
                acc8_u4(acc, *(const uint4*)&g_h2[(size_t)ed.x * DOUT + sub * 8]);
        }
    }
    float d = dinv_of(node);  // last read of g_degi[node]
    if (sub == 0) g_degi[node] = 0;
    if (gw == 0 && lane == 0) g_ovf_cnt = 0;

    float4 b0 = *(const float4*)&b2[sub * 8];
    float4 b1v = *(const float4*)&b2[sub * 8 + 4];
    float4 o0 = make_float4(d * acc[0] + b0.x, d * acc[1] + b0.y,
                            d * acc[2] + b0.z, d * acc[3] + b0.w);
    float4 o1 = make_float4(d * acc[4] + b1v.x, d * acc[5] + b1v.y,
                            d * acc[6] + b1v.z, d * acc[7] + b1v.w);
    *(float4*)&out[(size_t)node * DOUT + sub * 8]     = o0;
    *(float4*)&out[(size_t)node * DOUT + sub * 8 + 4] = o1;
}

extern "C" void kernel_launch(void* const* d_in, const int* in_sizes, int n_in,
                              void* d_out, int out_size) {
    const float* x  = (const float*)d_in[0];
    const void*  ei = d_in[1];
    const float* W1 = (const float*)d_in[2];
    const float* b1 = (const float*)d_in[3];
    const float* W2 = (const float*)d_in[4];
    const float* b2 = (const float*)d_in[5];
    float* out = (float*)d_out;

    const int n = in_sizes[0] / DIN;
    const int E = in_sizes[1] / 2;

    int eb = ((E + 1) / 2 + 255) / 256;
    int wb = (DIN * DHID + DHID * DOUT + 255) / 256;
    k_prep<<<eb + wb, 256>>>(ei, E, W1, W2, eb);

    k_gemm1<<<(n + 63) / 64, 256>>>(x, n);
    k_scatter1<<<(n * 32 + 255) / 256, 256>>>(b1, n);

    k_gemm2<<<(n + 63) / 64, 256>>>(n);
    int warps2 = (n + 3) / 4;
    k_scatter2<<<(warps2 * 32 + 255) / 256, 256>>>(b2, out, n);
}

// round 16
// speedup vs baseline: 1.0208x; 1.0208x over previous
#include <cuda_runtime.h>
#include <cuda_fp16.h>

#define NMAX 50000
#define BCAP 64
#define OVF_MAX 4096
#define DIN 128
#define DHID 128
#define DOUT 64

// g_degi is zero-initialized at module load and re-zeroed by k_scatter2 at the
// end of every call, so k_prep's atomicAdd-based bucketing sees zeros on every
// call (correctness run and every graph replay alike).
__device__ int    g_degi[NMAX];
__device__ int    g_srcs[NMAX * BCAP];   // stores src << 7 (byte offset of 128B row)
__device__ int2   g_ovf[OVF_MAX];        // raw (src, dst)
__device__ int    g_ovf_cnt;
__device__ __half g_h[NMAX * DHID];      // fp16: dinv * (x @ W1)      (256B rows)
__device__ __half g_in2[NMAX * DHID];    // fp16: relu(dinv*sum + b1)
__device__ __half g_h2[NMAX * DOUT];     // fp16: dinv * (in2 @ W2)    (128B rows)
__device__ __half g_w1t[DHID * DIN];     // W1^T [n][k] fp16
__device__ __half g_w2t[DOUT * DHID];    // W2^T [n][k] fp16

__device__ __forceinline__ void mma16(float* c, const unsigned* a, const unsigned* b) {
    asm volatile(
        "mma.sync.aligned.m16n8k16.row.col.f32.f16.f16.f32 "
        "{%0,%1,%2,%3},{%4,%5,%6,%7},{%8,%9},{%0,%1,%2,%3};"
        : "+f"(c[0]), "+f"(c[1]), "+f"(c[2]), "+f"(c[3])
        : "r"(a[0]), "r"(a[1]), "r"(a[2]), "r"(a[3]), "r"(b[0]), "r"(b[1]));
}

__device__ __forceinline__ float dinv_of(int row) {
    return rsqrtf((float)(g_degi[row] + 1));
}

__device__ __forceinline__ void acc4_u2(float* acc, uint2 u) {
    float2 f0 = __half22float2(*(__half2*)&u.x);
    float2 f1 = __half22float2(*(__half2*)&u.y);
    acc[0] += f0.x; acc[1] += f0.y; acc[2] += f1.x; acc[3] += f1.y;
}

__device__ __forceinline__ void acc4_pair(float* acc, uint2 a, uint2 b) {
    __half2 p0 = __hadd2(*(__half2*)&a.x, *(__half2*)&b.x);
    __half2 p1 = __hadd2(*(__half2*)&a.y, *(__half2*)&b.y);
    float2 f0 = __half22float2(p0);
    float2 f1 = __half22float2(p1);
    acc[0] += f0.x; acc[1] += f0.y; acc[2] += f1.x; acc[3] += f1.y;
}

__device__ __forceinline__ void acc8_u4(float* acc, uint4 a) {
    float2 f0 = __half22float2(*(__half2*)&a.x);
    float2 f1 = __half22float2(*(__half2*)&a.y);
    float2 f2 = __half22float2(*(__half2*)&a.z);
    float2 f3 = __half22float2(*(__half2*)&a.w);
    acc[0] += f0.x; acc[1] += f0.y; acc[2] += f1.x; acc[3] += f1.y;
    acc[4] += f2.x; acc[5] += f2.y; acc[6] += f3.x; acc[7] += f3.y;
}

__device__ __forceinline__ void acc8_pair(float* acc, uint4 a, uint4 b) {
    __half2 p0 = __hadd2(*(__half2*)&a.x, *(__half2*)&b.x);
    __half2 p1 = __hadd2(*(__half2*)&a.y, *(__half2*)&b.y);
    __half2 p2 = __hadd2(*(__half2*)&a.z, *(__half2*)&b.z);
    __half2 p3 = __hadd2(*(__half2*)&a.w, *(__half2*)&b.w);
    float2 f0 = __half22float2(p0), f1 = __half22float2(p1);
    float2 f2 = __half22float2(p2), f3 = __half22float2(p3);
    acc[0] += f0.x; acc[1] += f0.y; acc[2] += f1.x; acc[3] += f1.y;
    acc[4] += f2.x; acc[5] += f2.y; acc[6] += f3.x; acc[7] += f3.y;
}

// ---------------------------------------------------------------------------
// k_prep: edge bucketing blocks + weight transpose blocks (single launch).
// ---------------------------------------------------------------------------
__global__ void k_prep(const void* ei, int E,
                       const float* __restrict__ W1, const float* __restrict__ W2,
                       int nEdgeBlocks) {
    if ((int)blockIdx.x >= nEdgeBlocks) {
        int i = (blockIdx.x - nEdgeBlocks) * 256 + threadIdx.x;
        if (i < DIN * DHID) {
            int nn = i >> 7, k = i & 127;
            g_w1t[nn * DIN + k] = __float2half(W1[k * DHID + nn]);
        }
        int j = i - DIN * DHID;
        if (j >= 0 && j < DHID * DOUT) {
            int nn = j >> 7, k = j & 127;
            g_w2t[nn * DHID + k] = __float2half(W2[k * DOUT + nn]);
        }
        return;
    }

    __shared__ int s_is64;
    if (threadIdx.x == 0) {
        const unsigned* p32 = (const unsigned*)ei;
        int ok = 1;
        for (int j = 0; j < 64; j++)
            if (p32[2 * j + 1] != 0u) ok = 0;
        s_is64 = ok;
    }
    __syncthreads();
    int is64 = s_is64;

    int e = (blockIdx.x * blockDim.x + threadIdx.x) * 2;
    if (e >= E) return;
    int src0, dst0, src1 = 0, dst1 = 0;
    int has1 = (e + 1 < E);
    if (is64) {
        const long long* p = (const long long*)ei;
        src0 = (int)p[e];
        dst0 = (int)p[E + e];
        if (has1) { src1 = (int)p[e + 1]; dst1 = (int)p[E + e + 1]; }
    } else {
        const int* p = (const int*)ei;
        src0 = p[e];
        dst0 = p[E + e];
        if (has1) { src1 = p[e + 1]; dst1 = p[E + e + 1]; }
    }
    int slot0 = atomicAdd(&g_degi[dst0], 1);
    if (slot0 < BCAP) {
        g_srcs[dst0 * BCAP + slot0] = src0 << 7;   // pre-scaled byte offset
    } else {
        int o = atomicAdd(&g_ovf_cnt, 1);
        if (o < OVF_MAX) g_ovf[o] = make_int2(src0, dst0);
    }
    if (has1) {
        int slot1 = atomicAdd(&g_degi[dst1], 1);
        if (slot1 < BCAP) {
            g_srcs[dst1 * BCAP + slot1] = src1 << 7;
        } else {
            int o = atomicAdd(&g_ovf_cnt, 1);
            if (o < OVF_MAX) g_ovf[o] = make_int2(src1, dst1);
        }
    }
}

// ---------------------------------------------------------------------------
// GEMM1 (fp16 m16n8k16, full-K single-sync, fused fp32->fp16 x load)
// CTA 128x128, 8 warps (4m x 2n) — R14 best-benched shape.
// ---------------------------------------------------------------------------
__global__ __launch_bounds__(256) void k_gemm1(const float* __restrict__ x, int n) {
    __shared__ unsigned xs[128][68];
    __shared__ unsigned ws[128][68];

    const int t = threadIdx.x;
    const int lane = t & 31;
    const int warp = t >> 5;
    const int wm = warp >> 1;
    const int wn = warp & 1;
    const int tg = lane & 3;
    const int gi = lane >> 2;
    const int row0 = blockIdx.x * 128;

#pragma unroll
    for (int i = 0; i < 16; i++) {
        int idx = t + i * 256;
        int r = idx >> 5, q = idx & 31;
        float4 v = make_float4(0.f, 0.f, 0.f, 0.f);
        if (row0 + r < n)
            v = *(const float4*)&x[(size_t)(row0 + r) * DIN + q * 4];
        uint2 o;
        *(__half2*)&o.x = __floats2half2_rn(v.x, v.y);
        *(__half2*)&o.y = __floats2half2_rn(v.z, v.w);
        *(uint2*)&xs[r][q * 2] = o;
    }
#pragma unroll
    for (int i = 0; i < 8; i++) {
        int idx = t + i * 256;
        int c = idx >> 4, q = idx & 15;
        uint4 v = *(const uint4*)&g_w1t[c * DIN + q * 8];
        *(uint4*)&ws[c][q * 4] = v;
    }
    __syncthreads();

    float acc[2][8][4];
#pragma unroll
    for (int m = 0; m < 2; m++)
#pragma unroll
        for (int nn = 0; nn < 8; nn++)
#pragma unroll
            for (int j = 0; j < 4; j++) acc[m][nn][j] = 0.f;

#pragma unroll
    for (int ks = 0; ks < 8; ks++) {
        int k0 = ks * 8;
        unsigned a[2][4];
#pragma unroll
        for (int m = 0; m < 2; m++) {
            int r = wm * 32 + m * 16 + gi;
            a[m][0] = xs[r][k0 + tg];
            a[m][1] = xs[r + 8][k0 + tg];
            a[m][2] = xs[r][k0 + 4 + tg];
            a[m][3] = xs[r + 8][k0 + 4 + tg];
        }
#pragma unroll
        for (int nn = 0; nn < 8; nn++) {
            int c = wn * 64 + nn * 8 + gi;
            unsigned b[2];
            b[0] = ws[c][k0 + tg];
            b[1] = ws[c][k0 + 4 + tg];
            mma16(acc[0][nn], a[0], b);
            mma16(acc[1][nn], a[1], b);
        }
    }

#pragma unroll
    for (int m = 0; m < 2; m++) {
#pragma unroll
        for (int h = 0; h < 2; h++) {
            int row = row0 + wm * 32 + m * 16 + gi + h * 8;
            if (row < n) {
                float d = dinv_of(row);
#pragma unroll
                for (int nn = 0; nn < 8; nn++) {
                    int col = wn * 64 + nn * 8 + tg * 2;
                    __half2 o = __floats2half2_rn(acc[m][nn][h * 2 + 0] * d,
                                                  acc[m][nn][h * 2 + 1] * d);
                    *(__half2*)&g_h[(size_t)row * DHID + col] = o;
                }
            }
        }
    }
}

// ---------------------------------------------------------------------------
// scatter1 + layer-2 input prep (FROZEN shape): 1 warp/node, prescaled offsets.
// ---------------------------------------------------------------------------
__global__ __launch_bounds__(256, 8) void k_scatter1(const float* __restrict__ b1, int n) {
    int w = (blockIdx.x * blockDim.x + threadIdx.x) >> 5;
    int lane = threadIdx.x & 31;
    if (w >= n) return;
    int deg = g_degi[w];
    int nb = min(deg, BCAP);

    const char* hb = (const char*)g_h;
    const size_t lo = (size_t)(lane * 8);   // lane byte offset within 256B row

    float acc[4] = {0.f, 0.f, 0.f, 0.f};
    acc4_u2(acc, *(const uint2*)(hb + ((size_t)w << 8) + lo));

    for (int base = 0; base < nb; base += 32) {
        int cnt = min(nb - base, 32);
        int s = (lane < cnt) ? g_srcs[w * BCAP + base + lane] : 0;
        int i = 0;
        for (; i + 4 <= cnt; i += 4) {
            int s0 = __shfl_sync(0xffffffffu, s, i);
            int s1 = __shfl_sync(0xffffffffu, s, i + 1);
            int s2 = __shfl_sync(0xffffffffu, s, i + 2);
            int s3 = __shfl_sync(0xffffffffu, s, i + 3);
            uint2 u0 = *(const uint2*)(hb + ((size_t)(unsigned)s0 << 1) + lo);
            uint2 u1 = *(const uint2*)(hb + ((size_t)(unsigned)s1 << 1) + lo);
            uint2 u2 = *(const uint2*)(hb + ((size_t)(unsigned)s2 << 1) + lo);
            uint2 u3 = *(const uint2*)(hb + ((size_t)(unsigned)s3 << 1) + lo);
            acc4_pair(acc, u0, u1);
            acc4_pair(acc, u2, u3);
        }
        if (i + 2 <= cnt) {
            int s0 = __shfl_sync(0xffffffffu, s, i);
            int s1 = __shfl_sync(0xffffffffu, s, i + 1);
            uint2 u0 = *(const uint2*)(hb + ((size_t)(unsigned)s0 << 1) + lo);
            uint2 u1 = *(const uint2*)(hb + ((size_t)(unsigned)s1 << 1) + lo);
            acc4_pair(acc, u0, u1);
            i += 2;
        }
        if (i < cnt) {
            int s0 = __shfl_sync(0xffffffffu, s, i);
            acc4_u2(acc, *(const uint2*)(hb + ((size_t)(unsigned)s0 << 1) + lo));
        }
    }
    if (deg > BCAP) {  // correctness fallback, practically never taken
        int oc = min(g_ovf_cnt, OVF_MAX);
        for (int i = 0; i < oc; i++) {
            int2 ed = g_ovf[i];
            if (ed.y == w)
                acc4_u2(acc, *(const uint2*)(hb + ((size_t)ed.x << 8) + lo));
        }
    }
    float d = dinv_of(w);
    float4 bb = *(const float4*)&b1[lane * 4];
    float v0 = fmaxf(d * acc[0] + bb.x, 0.f);
    float v1 = fmaxf(d * acc[1] + bb.y, 0.f);
    float v2 = fmaxf(d * acc[2] + bb.z, 0.f);
    float v3 = fmaxf(d * acc[3] + bb.w, 0.f);
    uint2 o;
    *(__half2*)&o.x = __floats2half2_rn(v0, v1);
    *(__half2*)&o.y = __floats2half2_rn(v2, v3);
    *(uint2*)&g_in2[(size_t)w * DHID + lane * 4] = o;
}

// ---------------------------------------------------------------------------
// GEMM2 (fp16 m16n8k16, full-K single-sync) — R14 best-benched shape (128x64).
// ---------------------------------------------------------------------------
__global__ __launch_bounds__(256) void k_gemm2(int n) {
    __shared__ unsigned xs[128][68];
    __shared__ unsigned ws[64][68];

    const int t = threadIdx.x;
    const int lane = t & 31;
    const int warp = t >> 5;
    const int wm = warp >> 1;
    const int wn = warp & 1;
    const int tg = lane & 3;
    const int gi = lane >> 2;
    const int row0 = blockIdx.x * 128;

#pragma unroll
    for (int i = 0; i < 8; i++) {
        int idx = t + i * 256;
        int r = idx >> 4, q = idx & 15;
        uint4 v = make_uint4(0u, 0u, 0u, 0u);
        if (row0 + r < n)
            v = *(const uint4*)&g_in2[(size_t)(row0 + r) * DHID + q * 8];
        *(uint4*)&xs[r][q * 4] = v;
    }
#pragma unroll
    for (int i = 0; i < 4; i++) {
        int idx = t + i * 256;
        int c = idx >> 4, q = idx & 15;
        uint4 v = *(const uint4*)&g_w2t[c * DHID + q * 8];
        *(uint4*)&ws[c][q * 4] = v;
    }
    __syncthreads();

    float acc[2][4][4];
#pragma unroll
    for (int m = 0; m < 2; m++)
#pragma unroll
        for (int nn = 0; nn < 4; nn++)
#pragma unroll
            for (int j = 0; j < 4; j++) acc[m][nn][j] = 0.f;

#pragma unroll
    for (int ks = 0; ks < 8; ks++) {
        int k0 = ks * 8;
        unsigned a[2][4];
#pragma unroll
        for (int m = 0; m < 2; m++) {
            int r = wm * 32 + m * 16 + gi;
            a[m][0] = xs[r][k0 + tg];
            a[m][1] = xs[r + 8][k0 + tg];
            a[m][2] = xs[r][k0 + 4 + tg];
            a[m][3] = xs[r + 8][k0 + 4 + tg];
        }
#pragma unroll
        for (int nn = 0; nn < 4; nn++) {
            int c = wn * 32 + nn * 8 + gi;
            unsigned b[2];
            b[0] = ws[c][k0 + tg];
            b[1] = ws[c][k0 + 4 + tg];
            mma16(acc[0][nn], a[0], b);
            mma16(acc[1][nn], a[1], b);
        }
    }

#pragma unroll
    for (int m = 0; m < 2; m++) {
#pragma unroll
        for (int h = 0; h < 2; h++) {
            int row = row0 + wm * 32 + m * 16 + gi + h * 8;
            if (row < n) {
                float d = dinv_of(row);
#pragma unroll
                for (int nn = 0; nn < 4; nn++) {
                    int col = wn * 32 + nn * 8 + tg * 2;
                    __half2 o = __floats2half2_rn(acc[m][nn][h * 2 + 0] * d,
                                                  acc[m][nn][h * 2 + 1] * d);
                    *(__half2*)&g_h2[(size_t)row * DOUT + col] = o;
                }
            }
        }
    }
}

// ---------------------------------------------------------------------------
// scatter2 + final (FROZEN shape): 4 nodes/warp, 8 lanes each, prescaled offs.
// Also re-zeros g_degi[node] so k_prep sees zeros next call.
// ---------------------------------------------------------------------------
__global__ __launch_bounds__(256, 8) void k_scatter2(const float* __restrict__ b2,
                                                     float* __restrict__ out, int n) {
    int gw = (blockIdx.x * blockDim.x + threadIdx.x) >> 5;
    int lane = threadIdx.x & 31;
    int q   = lane >> 3;
    int sub = lane & 7;
    int node = gw * 4 + q;
    if (node >= n) return;
    unsigned gmask = 0xFFu << (q * 8);
    int deg = g_degi[node];
    int nb = min(deg, BCAP);

    const char* hb = (const char*)g_h2;
    const size_t lo = (size_t)(sub * 16);   // lane byte offset within 128B row

    float acc[8];
#pragma unroll
    for (int j = 0; j < 8; j++) acc[j] = 0.f;
    acc8_u4(acc, *(const uint4*)(hb + ((size_t)node << 7) + lo));

    for (int base = 0; base < nb; base += 8) {
        int cnt = min(nb - base, 8);
        int s = (sub < cnt) ? g_srcs[node * BCAP + base + sub] : 0;
        int i = 0;
        for (; i + 2 <= cnt; i += 2) {
            int s0 = __shfl_sync(gmask, s, q * 8 + i);
            int s1 = __shfl_sync(gmask, s, q * 8 + i + 1);
            uint4 a = *(const uint4*)(hb + (size_t)(unsigned)s0 + lo);
            uint4 b = *(const uint4*)(hb + (size_t)(unsigned)s1 + lo);
            acc8_pair(acc, a, b);
        }
        if (i < cnt) {
            int s0 = __shfl_sync(gmask, s, q * 8 + i);
            acc8_u4(acc, *(const uint4*)(hb + (size_t)(unsigned)s0 + lo));
        }
    }
    if (deg > BCAP) {
        int oc = min(g_ovf_cnt, OVF_MAX);
        for (int i = 0; i < oc; i++) {
            int2 ed = g_ovf[i];
            if (ed.y == node)
                acc8_u4(acc, *(const uint4*)(hb + ((size_t)ed.x << 7) + lo));
        }
    }
    float d = dinv_of(node);  // last read of g_degi[node]
    if (sub == 0) g_degi[node] = 0;
    if (gw == 0 && lane == 0) g_ovf_cnt = 0;

    float4 b0 = *(const float4*)&b2[sub * 8];
    float4 b1v = *(const float4*)&b2[sub * 8 + 4];
    float4 o0 = make_float4(d * acc[0] + b0.x, d * acc[1] + b0.y,
                            d * acc[2] + b0.z, d * acc[3] + b0.w);
    float4 o1 = make_float4(d * acc[4] + b1v.x, d * acc[5] + b1v.y,
                            d * acc[6] + b1v.z, d * acc[7] + b1v.w);
    *(float4*)&out[(size_t)node * DOUT + sub * 8]     = o0;
    *(float4*)&out[(size_t)node * DOUT + sub * 8 + 4] = o1;
}

extern "C" void kernel_launch(void* const* d_in, const int* in_sizes, int n_in,
                              void* d_out, int out_size) {
    const float* x  = (const float*)d_in[0];
    const void*  ei = d_in[1];
    const float* W1 = (const float*)d_in[2];
    const float* b1 = (const float*)d_in[3];
    const float* W2 = (const float*)d_in[4];
    const float* b2 = (const float*)d_in[5];
    float* out = (float*)d_out;

    const int n = in_sizes[0] / DIN;
    const int E = in_sizes[1] / 2;

    int eb = ((E + 1) / 2 + 255) / 256;
    int wb = (DIN * DHID + DHID * DOUT + 255) / 256;
    k_prep<<<eb + wb, 256>>>(ei, E, W1, W2, eb);

    k_gemm1<<<(n + 127) / 128, 256>>>(x, n);
    k_scatter1<<<(n * 32 + 255) / 256, 256>>>(b1, n);

    k_gemm2<<<(n + 127) / 128, 256>>>(n);
    int warps2 = (n + 3) / 4;
    k_scatter2<<<(warps2 * 32 + 255) / 256, 256>>>(b2, out, n);
}